// round 2
// baseline (speedup 1.0000x reference)
#include <cuda_runtime.h>

// SimpleTP: FullTensorProduct('1x1o','1x1o') of frac with itself, summed over N.
// Reduces to 6 quadratic moments s_ij = sum_n frac[n,i]*frac[n,j] (i<=j),
// then a fixed linear map to the 9 outputs (cross part is identically 0).

#define BLK 256
#define GRID_MAIN 1184          // ~8 blocks/SM on 148-SM B200
#define NACC 6

// Scratch for deterministic two-stage reduction: [block][6]
__device__ float g_part[GRID_MAIN * NACC];

__device__ __forceinline__ void acc3(float a, float b, float c,
                                     float& s00, float& s11, float& s22,
                                     float& s01, float& s02, float& s12) {
    s00 = fmaf(a, a, s00);
    s11 = fmaf(b, b, s11);
    s22 = fmaf(c, c, s22);
    s01 = fmaf(a, b, s01);
    s02 = fmaf(a, c, s02);
    s12 = fmaf(b, c, s12);
}

__device__ __forceinline__ void acc_vec3(const float4& v0, const float4& v1, const float4& v2,
                                         float& s00, float& s11, float& s22,
                                         float& s01, float& s02, float& s12) {
    acc3(v0.x, v0.y, v0.z, s00, s11, s22, s01, s02, s12);
    acc3(v0.w, v1.x, v1.y, s00, s11, s22, s01, s02, s12);
    acc3(v1.z, v1.w, v2.x, s00, s11, s22, s01, s02, s12);
    acc3(v2.y, v2.z, v2.w, s00, s11, s22, s01, s02, s12);
}

// Each "group" = 8 rows = 24 floats = 6 float4 loads (front-batched for MLP).
__global__ __launch_bounds__(BLK) void tp_moments_kernel(const float4* __restrict__ in4,
                                                         int num_groups8) {
    float s00 = 0.f, s11 = 0.f, s22 = 0.f, s01 = 0.f, s02 = 0.f, s12 = 0.f;

    int tid = blockIdx.x * BLK + threadIdx.x;
    int stride = gridDim.x * BLK;

    for (int g = tid; g < num_groups8; g += stride) {
        const float4* p = in4 + 6 * (size_t)g;
        float4 v0 = p[0];
        float4 v1 = p[1];
        float4 v2 = p[2];
        float4 v3 = p[3];
        float4 v4 = p[4];
        float4 v5 = p[5];
        acc_vec3(v0, v1, v2, s00, s11, s22, s01, s02, s12);
        acc_vec3(v3, v4, v5, s00, s11, s22, s01, s02, s12);
    }

    // warp reduction
    #pragma unroll
    for (int o = 16; o > 0; o >>= 1) {
        s00 += __shfl_down_sync(0xffffffffu, s00, o);
        s11 += __shfl_down_sync(0xffffffffu, s11, o);
        s22 += __shfl_down_sync(0xffffffffu, s22, o);
        s01 += __shfl_down_sync(0xffffffffu, s01, o);
        s02 += __shfl_down_sync(0xffffffffu, s02, o);
        s12 += __shfl_down_sync(0xffffffffu, s12, o);
    }

    __shared__ float sm[NACC][BLK / 32];
    int lane = threadIdx.x & 31;
    int w = threadIdx.x >> 5;
    if (lane == 0) {
        sm[0][w] = s00; sm[1][w] = s11; sm[2][w] = s22;
        sm[3][w] = s01; sm[4][w] = s02; sm[5][w] = s12;
    }
    __syncthreads();

    // one thread per accumulator folds the 8 warp partials
    if (threadIdx.x < NACC) {
        float t = 0.f;
        #pragma unroll
        for (int i = 0; i < BLK / 32; i++) t += sm[threadIdx.x][i];
        g_part[blockIdx.x * NACC + threadIdx.x] = t;
    }
}

__global__ __launch_bounds__(BLK) void tp_finalize_kernel(const float* __restrict__ in,
                                                          int total_floats,
                                                          float* __restrict__ out) {
    float s[NACC];
    #pragma unroll
    for (int k = 0; k < NACC; k++) s[k] = 0.f;

    // fold block partials
    for (int b = threadIdx.x; b < GRID_MAIN; b += BLK) {
        #pragma unroll
        for (int k = 0; k < NACC; k++) s[k] += g_part[b * NACC + k];
    }

    // tail rows (not covered by groups-of-8), handled by thread 0 only
    if (threadIdx.x == 0) {
        int num_rows = total_floats / 3;
        int covered = (num_rows / 8) * 8;
        for (int r = covered; r < num_rows; r++) {
            float a = in[3 * r + 0], b = in[3 * r + 1], c = in[3 * r + 2];
            s[0] += a * a; s[1] += b * b; s[2] += c * c;
            s[3] += a * b; s[4] += a * c; s[5] += b * c;
        }
    }

    // block reduce
    #pragma unroll
    for (int o = 16; o > 0; o >>= 1) {
        #pragma unroll
        for (int k = 0; k < NACC; k++) s[k] += __shfl_down_sync(0xffffffffu, s[k], o);
    }
    __shared__ float sm[NACC][BLK / 32];
    int lane = threadIdx.x & 31;
    int w = threadIdx.x >> 5;
    if (lane == 0) {
        #pragma unroll
        for (int k = 0; k < NACC; k++) sm[k][w] = s[k];
    }
    __syncthreads();

    if (threadIdx.x == 0) {
        float t[NACC];
        #pragma unroll
        for (int k = 0; k < NACC; k++) {
            t[k] = 0.f;
            #pragma unroll
            for (int i = 0; i < BLK / 32; i++) t[k] += sm[k][i];
        }
        const float s00 = t[0], s11 = t[1], s22 = t[2];
        const float s01 = t[3], s02 = t[4], s12 = t[5];
        const float INV_SQRT3 = 0.57735026918962576f;
        const float SQRT2     = 1.41421356237309505f;
        const float INV_SQRT6 = 0.40824829046386302f;
        const float INV_SQRT2 = 0.70710678118654752f;

        out[0] = (s00 + s11 + s22) * INV_SQRT3;       // 0e: dot/sqrt(3)
        out[1] = 0.f;                                 // 1e: cross(x,x) = 0
        out[2] = 0.f;
        out[3] = 0.f;
        out[4] = SQRT2 * s02;                         // 2e m=-2
        out[5] = SQRT2 * s01;                         // 2e m=-1
        out[6] = (2.f * s11 - s00 - s22) * INV_SQRT6; // 2e m=0
        out[7] = SQRT2 * s12;                         // 2e m=+1
        out[8] = (s22 - s00) * INV_SQRT2;             // 2e m=+2
    }
}

extern "C" void kernel_launch(void* const* d_in, const int* in_sizes, int n_in,
                              void* d_out, int out_size) {
    const float* frac = (const float*)d_in[0];
    float* out = (float*)d_out;
    int total_floats = in_sizes[0];          // N*3
    int num_groups8 = total_floats / 24;     // groups of 8 rows

    tp_moments_kernel<<<GRID_MAIN, BLK>>>((const float4*)frac, num_groups8);
    tp_finalize_kernel<<<1, BLK>>>(frac, total_floats, out);
}